// round 15
// baseline (speedup 1.0000x reference)
#include <cuda_runtime.h>
#include <cstdint>

// Problem constants (fixed by setup_inputs: B=2, Lq=16384, D=1024, M=64, H=16)
#define DMODEL 1024
#define ROWS   128            // B*M flattened rows
#define TPF    256            // Lq / M  (tokens per frame)

#define MG     8              // row-groups (16 rows each)
#define NT     16             // column tiles (64 cols each)
#define GR     16             // rows per group
#define GC     64             // cols per tile
#define KC     64             // k-chunk
#define NCHUNK (DMODEL / KC)  // 16
#define GRID   (MG * NT)      // 128 CTAs
#define NTHR   512

// Scratch (static __device__ arrays — no runtime allocation)
__device__ float g_V[ROWS * DMODEL];   // v = context @ Wkv_v + bkv_v

// Per-group barrier counters. MONOTONIC across launches — never reset
// (reset schemes deadlock: a CTA still polling can observe the zeroed
// counter). Each launch's cohort releases at the next multiple of NT.
__device__ unsigned g_gbar[MG];

__device__ __forceinline__ void group_barrier(int m) {
    __syncthreads();
    if (threadIdx.x == 0) {
        __threadfence();                                   // release prior writes
        const unsigned my = atomicAdd(&g_gbar[m], 1u) + 1u;
        const unsigned target = ((my + NT - 1u) / NT) * NT;
        while (*(volatile unsigned*)&g_gbar[m] < target) { __nanosleep(32); }
        __threadfence();                                   // acquire others' writes
    }
    __syncthreads();
}

// ---------------------------------------------------------------------------
// tf32 helpers (mma.sync — baseline PTX, works at compute_100)
// ---------------------------------------------------------------------------
__device__ __forceinline__ uint32_t f2tf32(float f) {
    uint32_t r;
    asm("cvt.rna.tf32.f32 %0, %1;" : "=r"(r) : "f"(f));
    return r;
}
__device__ __forceinline__ void cvt_hilo(float f, uint32_t& hi, uint32_t& lo) {
    hi = f2tf32(f);
    lo = f2tf32(f - __uint_as_float(hi));
}
__device__ __forceinline__ void mma_tf32(float* d, const uint32_t* a, const uint32_t* b) {
    asm volatile(
        "mma.sync.aligned.m16n8k8.row.col.f32.tf32.tf32.f32 "
        "{%0,%1,%2,%3}, {%4,%5,%6,%7}, {%8,%9}, {%0,%1,%2,%3};"
        : "+f"(d[0]), "+f"(d[1]), "+f"(d[2]), "+f"(d[3])
        : "r"(a[0]), "r"(a[1]), "r"(a[2]), "r"(a[3]), "r"(b[0]), "r"(b[1]));
}

// ---------------------------------------------------------------------------
// SMEM layout (bytes):
//  a_hi/a_lo: [16 rows][1028 k]   fragment banks (4g + r): conflict-free
//  W chunks:  2 buffers x (hi+lo) of [64 k][72 n]; fragment banks (8r + g): CF
//  zbuf:      [16][68] combine + broadcast staging
// ---------------------------------------------------------------------------
#define A_LD 1028
#define W_LD 72
#define Z_LD 68
#define SM_AH 0
#define SM_AL (GR * A_LD * 4)                  // 65792
#define SM_W  (2 * GR * A_LD * 4)              // 131584
#define WHALF (KC * W_LD * 4)                  // 18432
#define WBUF  (2 * WHALF)                      // 36864 (hi+lo)
#define SM_ZB (SM_W + 2 * WBUF)                // 205312
#define SMEM_TOTAL (SM_ZB + GR * Z_LD * 4)     // 209664

// ---------------------------------------------------------------------------
// Full-K GEMM tile: z16x64 = Arows[16 x 1024] @ W[1024, 64-col tile] + bias.
// 16 warps: nw = wid&7 (8-col tile), kh = wid>>3 (k-half of each chunk).
// Two accumulator chains per warp (even/odd ksteps) for MMA latency hiding.
// mode 0: write result to g_V (rows 16m..); mode 1: leave result in zbuf.
// 3-pass tf32 hi/lo for fp32-grade accuracy. Deterministic fixed-order sums.
// ---------------------------------------------------------------------------
__device__ void gemm_rowtile(const float* __restrict__ Arows,
                             const float* __restrict__ W, int ldw, int woff,
                             const float* __restrict__ bias,   // pre-offset to tile col 0
                             int mode, int m, char* sm,
                             float* __restrict__ vout)         // g_V + row/col offset base
{
    const int tid  = threadIdx.x;
    const int wid  = tid >> 5;
    const int lane = tid & 31;

    float* a_hi = (float*)(sm + SM_AH);
    float* a_lo = (float*)(sm + SM_AL);

    // --- Stage A [16 rows][1024 k] as tf32 hi/lo (once) ---
    {
        const int row = tid >> 5;              // 0..15
        const int kb  = (tid & 31) * 32;       // 32 k per thread
        const float* ap = Arows + (size_t)row * DMODEL + kb;
        float* dh = a_hi + row * A_LD + kb;
        float* dl = a_lo + row * A_LD + kb;
#pragma unroll
        for (int c = 0; c < 8; c++) {
            float4 f = __ldcg((const float4*)(ap + c * 4));
            uint32_t h[4], l[4];
            cvt_hilo(f.x, h[0], l[0]);
            cvt_hilo(f.y, h[1], l[1]);
            cvt_hilo(f.z, h[2], l[2]);
            cvt_hilo(f.w, h[3], l[3]);
            *(uint4*)(dh + c * 4) = make_uint4(h[0], h[1], h[2], h[3]);
            *(uint4*)(dl + c * 4) = make_uint4(l[0], l[1], l[2], l[3]);
        }
    }

    // W staging mapping: thread -> (k-row kr, 8 cols at cb)
    const int kr = tid >> 3;                   // 0..63
    const int cb = (tid & 7) * 8;              // 0..56

    // --- Stage W chunk 0 into buffer 0 ---
    {
        const float* wp = W + (size_t)kr * ldw + woff + cb;
        float4 f0 = __ldg((const float4*)wp);
        float4 f1 = __ldg((const float4*)(wp + 4));
        float* wh = (float*)(sm + SM_W);
        float* wl = (float*)(sm + SM_W + WHALF);
        uint32_t h[4], l[4];
        cvt_hilo(f0.x, h[0], l[0]); cvt_hilo(f0.y, h[1], l[1]);
        cvt_hilo(f0.z, h[2], l[2]); cvt_hilo(f0.w, h[3], l[3]);
        *(uint4*)(wh + kr * W_LD + cb) = make_uint4(h[0], h[1], h[2], h[3]);
        *(uint4*)(wl + kr * W_LD + cb) = make_uint4(l[0], l[1], l[2], l[3]);
        cvt_hilo(f1.x, h[0], l[0]); cvt_hilo(f1.y, h[1], l[1]);
        cvt_hilo(f1.z, h[2], l[2]); cvt_hilo(f1.w, h[3], l[3]);
        *(uint4*)(wh + kr * W_LD + cb + 4) = make_uint4(h[0], h[1], h[2], h[3]);
        *(uint4*)(wl + kr * W_LD + cb + 4) = make_uint4(l[0], l[1], l[2], l[3]);
    }
    __syncthreads();

    const int nw = wid & 7;
    const int kh = wid >> 3;
    const int g  = lane >> 2;
    const int r  = lane & 3;

    float aE[4] = {0.f, 0.f, 0.f, 0.f};
    float aO[4] = {0.f, 0.f, 0.f, 0.f};

    const uint32_t* AH = (const uint32_t*)a_hi;
    const uint32_t* AL = (const uint32_t*)a_lo;

    for (int c = 0; c < NCHUNK; c++) {
        // Prefetch next W chunk (overlaps MMA)
        float4 n0, n1;
        if (c + 1 < NCHUNK) {
            const float* wp = W + (size_t)((c + 1) * KC + kr) * ldw + woff + cb;
            n0 = __ldg((const float4*)wp);
            n1 = __ldg((const float4*)(wp + 4));
        }

        const uint32_t* WH = (const uint32_t*)(sm + SM_W + (c & 1) * WBUF);
        const uint32_t* WL = (const uint32_t*)(sm + SM_W + (c & 1) * WBUF + WHALF);

#pragma unroll
        for (int j = 0; j < 4; j++) {
            const int kl = 32 * kh + 8 * j;    // k within chunk
            const int ka = c * KC + kl;        // global k
            uint32_t ah[4], al[4], bh[2], bl[2];
            ah[0] = AH[g * A_LD + ka + r];
            ah[1] = AH[(g + 8) * A_LD + ka + r];
            ah[2] = AH[g * A_LD + ka + r + 4];
            ah[3] = AH[(g + 8) * A_LD + ka + r + 4];
            al[0] = AL[g * A_LD + ka + r];
            al[1] = AL[(g + 8) * A_LD + ka + r];
            al[2] = AL[g * A_LD + ka + r + 4];
            al[3] = AL[(g + 8) * A_LD + ka + r + 4];
            bh[0] = WH[(kl + r) * W_LD + 8 * nw + g];
            bh[1] = WH[(kl + r + 4) * W_LD + 8 * nw + g];
            bl[0] = WL[(kl + r) * W_LD + 8 * nw + g];
            bl[1] = WL[(kl + r + 4) * W_LD + 8 * nw + g];

            float* acc = (j & 1) ? aO : aE;
            mma_tf32(acc, ah, bh);   // hi*hi
            mma_tf32(acc, ah, bl);   // hi*lo
            mma_tf32(acc, al, bh);   // lo*hi
        }

        // Stage next chunk into the other buffer
        if (c + 1 < NCHUNK) {
            float* wh = (float*)(sm + SM_W + ((c + 1) & 1) * WBUF);
            float* wl = wh + WHALF / 4;
            uint32_t h[4], l[4];
            cvt_hilo(n0.x, h[0], l[0]); cvt_hilo(n0.y, h[1], l[1]);
            cvt_hilo(n0.z, h[2], l[2]); cvt_hilo(n0.w, h[3], l[3]);
            *(uint4*)(wh + kr * W_LD + cb) = make_uint4(h[0], h[1], h[2], h[3]);
            *(uint4*)(wl + kr * W_LD + cb) = make_uint4(l[0], l[1], l[2], l[3]);
            cvt_hilo(n1.x, h[0], l[0]); cvt_hilo(n1.y, h[1], l[1]);
            cvt_hilo(n1.z, h[2], l[2]); cvt_hilo(n1.w, h[3], l[3]);
            *(uint4*)(wh + kr * W_LD + cb + 4) = make_uint4(h[0], h[1], h[2], h[3]);
            *(uint4*)(wl + kr * W_LD + cb + 4) = make_uint4(l[0], l[1], l[2], l[3]);
            __syncthreads();
        }
    }

    // --- Combine k-halves + bias; write v (mode 0) or zbuf (mode 1) ---
    float s0 = aE[0] + aO[0], s1 = aE[1] + aO[1];
    float s2 = aE[2] + aO[2], s3 = aE[3] + aO[3];
    float* zb = (float*)(sm + SM_ZB);
    const int col = 8 * nw + 2 * r;

    if (kh == 1) {
        *(float2*)&zb[g * Z_LD + col]       = make_float2(s0, s1);
        *(float2*)&zb[(g + 8) * Z_LD + col] = make_float2(s2, s3);
    }
    __syncthreads();
    if (kh == 0) {
        const float2 q0 = *(float2*)&zb[g * Z_LD + col];
        const float2 q1 = *(float2*)&zb[(g + 8) * Z_LD + col];
        const float b0 = __ldg(bias + col);
        const float b1 = __ldg(bias + col + 1);
        const float z00 = s0 + q0.x + b0, z01 = s1 + q0.y + b1;
        const float z10 = s2 + q1.x + b0, z11 = s3 + q1.y + b1;
        if (mode == 0) {
            float* vp = vout + (size_t)g * DMODEL + col;
            *(float2*)vp                 = make_float2(z00, z01);
            *(float2*)(vp + 8 * DMODEL)  = make_float2(z10, z11);
        } else {
            *(float2*)&zb[g * Z_LD + col]       = make_float2(z00, z01);
            *(float2*)&zb[(g + 8) * Z_LD + col] = make_float2(z10, z11);
        }
    }
}

// ---------------------------------------------------------------------------
// Fused kernel: CTA (m = bid>>4, n = bid&15) owns z[16m:16m+16, 64n:64n+64].
//   gemm1 -> g_V | 16-CTA group barrier | gemm2 -> zbuf | broadcast.
// No grid-wide barriers: row-groups are independent and drift freely,
// overlapping GEMM compute with other groups' broadcast stores.
// ---------------------------------------------------------------------------
__global__ __launch_bounds__(NTHR, 1)
void fused_all(const float* __restrict__ context,
               const float* __restrict__ Wkv,
               const float* __restrict__ bkv,
               const float* __restrict__ Wo,
               const float* __restrict__ bo,
               float* __restrict__ out)
{
    extern __shared__ char sm[];
    const int m = blockIdx.x >> 4;
    const int n = blockIdx.x & 15;

    // GEMM1: v tile = context rows @ Wkv[:, 1024 + tile] + bkv[1024 + tile]
    gemm_rowtile(context + (size_t)(GR * m) * DMODEL,
                 Wkv, 2 * DMODEL, DMODEL + GC * n,
                 bkv + DMODEL + GC * n, 0, m, sm,
                 g_V + (size_t)(GR * m) * DMODEL + GC * n);

    group_barrier(m);   // z rows need all 1024 v-cols of this group

    // GEMM2: z tile = g_V rows @ Wo[:, tile] + bo[tile]  (result -> zbuf)
    gemm_rowtile(g_V + (size_t)(GR * m) * DMODEL,
                 Wo, DMODEL, GC * n,
                 bo + GC * n, 1, m, sm, nullptr);
    __syncthreads();

    // Broadcast: out rows [4096m, 4096(m+1)), cols [64n, 64n+64).
    // out row lr gets z local row lr>>8.
    {
        const int tid = threadIdx.x;
        const int f4c = tid & 15;              // 16 float4 = 64 cols
        const int s   = tid >> 4;              // 0..31 row slots
        const float* zb = (const float*)(sm + SM_ZB);
        float* gb = out + (size_t)(4096 * m) * DMODEL + GC * n + 4 * f4c;

#pragma unroll 4
        for (int zr = 0; zr < GR; zr++) {
            const float4 zv = *(const float4*)&zb[zr * Z_LD + 4 * f4c];
            float* rp = gb + (size_t)(zr * 256 + s) * DMODEL;
#pragma unroll
            for (int rep = 0; rep < 8; rep++)
                *(float4*)(rp + (size_t)(rep * 32) * DMODEL) = zv;
        }
    }
}

// ---------------------------------------------------------------------------
// Inputs (metadata order): 0:x 1:context 2:Wq 3:bq 4:Wkv 5:bkv 6:Wo 7:bo
// x, Wq, bq are DEAD in the reference (q is never used).
// ---------------------------------------------------------------------------
extern "C" void kernel_launch(void* const* d_in, const int* in_sizes, int n_in,
                              void* d_out, int out_size)
{
    (void)in_sizes; (void)n_in; (void)out_size;

    const float* context = (const float*)d_in[1];
    const float* Wkv     = (const float*)d_in[4];
    const float* bkv     = (const float*)d_in[5];
    const float* Wo      = (const float*)d_in[6];
    const float* bo      = (const float*)d_in[7];
    float* out           = (float*)d_out;

    static bool attr_set = false;
    if (!attr_set) {
        cudaFuncSetAttribute(fused_all, cudaFuncAttributeMaxDynamicSharedMemorySize, SMEM_TOTAL);
        attr_set = true;
    }

    fused_all<<<GRID, NTHR, SMEM_TOTAL>>>(context, Wkv, bkv, bo ? Wo : Wo, bo, out);
}

// round 16
// speedup vs baseline: 1.4557x; 1.4557x over previous
#include <cuda_runtime.h>
#include <cstdint>

// Problem constants (fixed by setup_inputs: B=2, Lq=16384, D=1024, M=64, H=16)
#define DMODEL 1024
#define ROWS   128            // B*M flattened rows
#define TPF    256            // Lq / M  (tokens per frame)

#define KSPLIT 16             // split-K factor
#define BK     64             // K per GEMM job
#define BN     128            // cols per GEMM job
#define NTILE  (DMODEL / BN)  // 8 column tiles
#define NJOB   128            // GEMM/reduce jobs
#define GRID   148            // persistent CTAs = all SMs (1 CTA/SM, wave-1)
#define NTHR   512            // 16 warps, 4/SMSP

// Scratch (static __device__ arrays — no runtime allocation)
__device__ float g_P[KSPLIT * ROWS * DMODEL];  // split-K partials (8 MB)
__device__ float g_V[ROWS * DMODEL];           // v = context @ Wkv_v + bkv_v
__device__ float g_Z[ROWS * DMODEL];           // z = v @ Wo + bo

// Grid-barrier state. MONOTONIC across launches — never reset (reset schemes
// deadlock: a CTA still polling can observe the zeroed counter). Each
// launch's cohort releases at the next multiple of GRID.
__device__ unsigned g_bar[8];

__device__ __forceinline__ void grid_barrier(int ph) {
    __syncthreads();
    if (threadIdx.x == 0) {
        __threadfence();                                   // release prior writes
        const unsigned my = atomicAdd(&g_bar[ph], 1u) + 1u;
        const unsigned target = ((my + GRID - 1u) / GRID) * GRID;
        while (*(volatile unsigned*)&g_bar[ph] < target) { __nanosleep(32); }
        __threadfence();                                   // acquire others' writes
    }
    __syncthreads();
}

// ---------------------------------------------------------------------------
// tf32 helpers (mma.sync — baseline PTX, works at compute_100)
// ---------------------------------------------------------------------------
__device__ __forceinline__ uint32_t f2tf32(float f) {
    uint32_t r;
    asm("cvt.rna.tf32.f32 %0, %1;" : "=r"(r) : "f"(f));
    return r;
}
__device__ __forceinline__ void cvt_hilo(float f, uint32_t& hi, uint32_t& lo) {
    hi = f2tf32(f);
    lo = f2tf32(f - __uint_as_float(hi));
}
__device__ __forceinline__ void mma_tf32(float* d, const uint32_t* a, const uint32_t* b) {
    asm volatile(
        "mma.sync.aligned.m16n8k8.row.col.f32.tf32.tf32.f32 "
        "{%0,%1,%2,%3}, {%4,%5,%6,%7}, {%8,%9}, {%0,%1,%2,%3};"
        : "+f"(d[0]), "+f"(d[1]), "+f"(d[2]), "+f"(d[3])
        : "r"(a[0]), "r"(a[1]), "r"(a[2]), "r"(a[3]), "r"(b[0]), "r"(b[1]));
}

// ---------------------------------------------------------------------------
// SMEM layout (dynamic):
//  a_hi/a_lo: [128 m][68 k]   bank (4g+r): conflict-free fragment reads
//  b_hi/b_lo: [64 k][136 n]   bank (8r+8nt+g): conflict-free fragment reads
// ---------------------------------------------------------------------------
#define A_LD 68
#define B_LD 136
#define SM_AH 0
#define SM_AL (SM_AH + ROWS * A_LD * 4)            // 34816
#define SM_BH (SM_AL + ROWS * A_LD * 4)            // 69632
#define SM_BL (SM_BH + BK * B_LD * 4)              // 104448
#define SMEM_TOTAL (SM_BL + BK * B_LD * 4)         // 139264

// ---------------------------------------------------------------------------
// Stage W tile [64 k][128 n] as tf32 hi/lo into b_hi/b_lo (coalesced).
// ---------------------------------------------------------------------------
__device__ void stage_w(const float* __restrict__ W, int ldw, int woff,
                        int j0, int k0, char* sm)
{
    float* b_hi = (float*)(sm + SM_BH);
    float* b_lo = (float*)(sm + SM_BL);
    const int tid = threadIdx.x;
    const int kl  = tid >> 5;          // 0..15
    const int n   = (tid & 31) * 4;
#pragma unroll
    for (int it = 0; it < 4; it++) {
        const int k = it * 16 + kl;
        float4 f = *(const float4*)(W + (size_t)(k0 + k) * ldw + woff + j0 + n);
        uint32_t h[4], l[4];
        cvt_hilo(f.x, h[0], l[0]);
        cvt_hilo(f.y, h[1], l[1]);
        cvt_hilo(f.z, h[2], l[2]);
        cvt_hilo(f.w, h[3], l[3]);
        *(uint4*)(b_hi + k * B_LD + n) = make_uint4(h[0], h[1], h[2], h[3]);
        *(uint4*)(b_lo + k * B_LD + n) = make_uint4(l[0], l[1], l[2], l[3]);
    }
}

// ---------------------------------------------------------------------------
// One split-K GEMM job: g_P[ks][0:128][j0:+128] = A[:, k-slice] @ W[slice, cols]
// CTA id -> (jt = id & 7, ks = id >> 3). 16 warps as 4(M) x 4(N), tile 32x32.
// 3-pass tf32 hi/lo for fp32-grade accuracy. B tile must already be staged
// when do_stage_w == 0 (pre-staged while buffers were free).
// ---------------------------------------------------------------------------
__device__ void gemm_job(const float* __restrict__ A,
                         const float* __restrict__ W,
                         int ldw, int woff, int do_stage_w, char* sm)
{
    float* a_hi = (float*)(sm + SM_AH);
    float* a_lo = (float*)(sm + SM_AL);

    const int tid  = threadIdx.x;
    const int wid  = tid >> 5;
    const int lane = tid & 31;
    const int j0   = (blockIdx.x & (NTILE - 1)) * BN;
    const int ks0  = blockIdx.x >> 3;
    const int k0   = ks0 * BK;

    // --- Stage A tile [128 m][64 k] as tf32 hi/lo (512 thr: 16 floats each) ---
    {
        const int row = tid >> 2;
        const int kb  = (tid & 3) * 16;
        const float* ap = A + (size_t)row * DMODEL + k0 + kb;
        float* dh = a_hi + row * A_LD + kb;
        float* dl = a_lo + row * A_LD + kb;
#pragma unroll
        for (int c = 0; c < 4; c++) {
            float4 f = *(const float4*)(ap + c * 4);
            uint32_t h[4], l[4];
            cvt_hilo(f.x, h[0], l[0]);
            cvt_hilo(f.y, h[1], l[1]);
            cvt_hilo(f.z, h[2], l[2]);
            cvt_hilo(f.w, h[3], l[3]);
            *(uint4*)(dh + c * 4) = make_uint4(h[0], h[1], h[2], h[3]);
            *(uint4*)(dl + c * 4) = make_uint4(l[0], l[1], l[2], l[3]);
        }
    }

    if (do_stage_w) stage_w(W, ldw, woff, j0, k0, sm);
    __syncthreads();

    const int m0 = (wid >> 2) * 32;      // 4 M-groups
    const int n0 = (wid & 3) * 32;       // 4 N-groups
    const int g  = lane >> 2;
    const int r  = lane & 3;

    float acc[2][4][4];
#pragma unroll
    for (int mt = 0; mt < 2; mt++)
#pragma unroll
        for (int nt = 0; nt < 4; nt++)
#pragma unroll
            for (int i = 0; i < 4; i++) acc[mt][nt][i] = 0.0f;

    const uint32_t* ah_s = (const uint32_t*)a_hi;
    const uint32_t* al_s = (const uint32_t*)a_lo;
    const uint32_t* bh_s = (const uint32_t*)(sm + SM_BH);
    const uint32_t* bl_s = (const uint32_t*)(sm + SM_BL);

#pragma unroll
    for (int ks = 0; ks < 8; ks++) {
        const int kk = ks * 8 + r;
        uint32_t ah[2][4], al[2][4];
#pragma unroll
        for (int mt = 0; mt < 2; mt++) {
            const int mrow = m0 + mt * 16 + g;
            ah[mt][0] = ah_s[mrow * A_LD + kk];
            ah[mt][1] = ah_s[(mrow + 8) * A_LD + kk];
            ah[mt][2] = ah_s[mrow * A_LD + kk + 4];
            ah[mt][3] = ah_s[(mrow + 8) * A_LD + kk + 4];
            al[mt][0] = al_s[mrow * A_LD + kk];
            al[mt][1] = al_s[(mrow + 8) * A_LD + kk];
            al[mt][2] = al_s[mrow * A_LD + kk + 4];
            al[mt][3] = al_s[(mrow + 8) * A_LD + kk + 4];
        }
#pragma unroll
        for (int nt = 0; nt < 4; nt++) {
            const int ncol = n0 + nt * 8 + g;
            uint32_t bh[2], bl[2];
            bh[0] = bh_s[(ks * 8 + r) * B_LD + ncol];
            bh[1] = bh_s[(ks * 8 + r + 4) * B_LD + ncol];
            bl[0] = bl_s[(ks * 8 + r) * B_LD + ncol];
            bl[1] = bl_s[(ks * 8 + r + 4) * B_LD + ncol];
#pragma unroll
            for (int mt = 0; mt < 2; mt++) {
                mma_tf32(acc[mt][nt], ah[mt], bh);   // hi*hi
                mma_tf32(acc[mt][nt], ah[mt], bl);   // hi*lo
                mma_tf32(acc[mt][nt], al[mt], bh);   // lo*hi
            }
        }
    }

    float* pbase = g_P + (size_t)ks0 * (ROWS * DMODEL) + j0;
#pragma unroll
    for (int mt = 0; mt < 2; mt++) {
        const int mrow = m0 + mt * 16 + g;
#pragma unroll
        for (int nt = 0; nt < 4; nt++) {
            const int ncol = n0 + nt * 8 + 2 * r;
            *(float2*)(pbase + (size_t)mrow * DMODEL + ncol) =
                make_float2(acc[mt][nt][0], acc[mt][nt][1]);
            *(float2*)(pbase + (size_t)(mrow + 8) * DMODEL + ncol) =
                make_float2(acc[mt][nt][2], acc[mt][nt][3]);
        }
    }
    __syncthreads();   // smem reuse safety before next phase
}

// ---------------------------------------------------------------------------
// Reduce 16 partials + bias for row (blockIdx.x) -> dst. 512 threads:
// halves each sum 8 slices, deterministic smem combine (bias + lo8 + hi8).
// Uses smem offset 0 (a_hi region — free between GEMM phases).
// ---------------------------------------------------------------------------
__device__ void reduce_job(const float* __restrict__ bias, int boff, float* dst, char* sm)
{
    float4* red = (float4*)sm;                            // 256 * 16 B = 4 KB

    const int tid  = threadIdx.x;
    const int el   = tid & 255;
    const int half = tid >> 8;                            // 0 or 1
    const int idx  = blockIdx.x * 256 + el;               // float4 index (row = bid)

    const float4* pp = (const float4*)g_P + (size_t)half * 8 * (ROWS * DMODEL / 4) + idx;
    float4 s = make_float4(0.f, 0.f, 0.f, 0.f);
#pragma unroll
    for (int p = 0; p < 8; p++) {
        const float4 v = pp[(size_t)p * (ROWS * DMODEL / 4)];
        s.x += v.x; s.y += v.y; s.z += v.z; s.w += v.w;
    }

    if (half == 1) red[el] = s;
    __syncthreads();
    if (half == 0) {
        const float* bp = bias + boff + el * 4;
        const float4 hi = red[el];
        float4 acc = make_float4(__ldg(bp)     + s.x + hi.x,
                                 __ldg(bp + 1) + s.y + hi.y,
                                 __ldg(bp + 2) + s.z + hi.z,
                                 __ldg(bp + 3) + s.w + hi.w);
        ((float4*)dst)[idx] = acc;
    }
    __syncthreads();   // smem reuse safety
}

// ---------------------------------------------------------------------------
// Persistent fused kernel on all 148 SMs:
//   [bid<128] gemm1 + pre-stage Wo | bar | [bid<128] reduce+bkv | bar |
//   [bid<128] gemm2 (W pre-staged) | bar | [bid<128] reduce+bo  | bar |
//   broadcast: 1024 (row, chunk) units grid-strided over ALL 148 CTAs.
// ---------------------------------------------------------------------------
__global__ __launch_bounds__(NTHR, 1)
void fused_all(const float* __restrict__ context,
               const float* __restrict__ Wkv,
               const float* __restrict__ bkv,
               const float* __restrict__ Wo,
               const float* __restrict__ bo,
               float* __restrict__ out)
{
    extern __shared__ char sm[];
    const bool worker = blockIdx.x < NJOB;

    // Phase A: v-partials = context @ Wkv[:, 1024:2048]
    if (worker) {
        gemm_job(context, Wkv, 2 * DMODEL, DMODEL, 1, sm);
        // Pre-stage Wo tile for phase C now that B buffers are free; the
        // LDG+cvt latency overlaps barrier-0 wait + reduce + barrier-1 wait.
        stage_w(Wo, DMODEL, 0,
                (blockIdx.x & (NTILE - 1)) * BN, (blockIdx.x >> 3) * BK, sm);
    }
    grid_barrier(0);

    // Phase B: g_V row bid = sum(partials) + bkv[1024:]
    if (worker) reduce_job(bkv, DMODEL, g_V, sm);
    grid_barrier(1);

    // Phase C: z-partials = g_V @ Wo (B tile already staged)
    if (worker) gemm_job(g_V, nullptr, 0, 0, 0, sm);
    grid_barrier(2);

    // Phase D: g_Z row bid = sum(partials) + bo
    if (worker) reduce_job(bo, 0, g_Z, sm);
    grid_barrier(3);

    // Phase E: broadcast — 1024 units (row g, 32-row chunk rc) over 148 CTAs.
    {
        const int col  = threadIdx.x & 255;      // float4 column
        const int half = threadIdx.x >> 8;       // 0/1 -> 16-row half of chunk
        for (int u = blockIdx.x; u < ROWS * (TPF / 32); u += GRID) {
            const int gg = u >> 3;               // 0..127
            const int rc = u & 7;                // 0..7
            const float4 s = __ldg((const float4*)g_Z + (size_t)gg * (DMODEL / 4) + col);
            float4* op = (float4*)out +
                ((size_t)gg * TPF + rc * 32 + half * 16) * (DMODEL / 4) + col;
#pragma unroll
            for (int r = 0; r < 16; r++)
                op[(size_t)r * (DMODEL / 4)] = s;
        }
    }
}

// ---------------------------------------------------------------------------
// Inputs (metadata order): 0:x 1:context 2:Wq 3:bq 4:Wkv 5:bkv 6:Wo 7:bo
// x, Wq, bq are DEAD in the reference (q is never used).
// ---------------------------------------------------------------------------
extern "C" void kernel_launch(void* const* d_in, const int* in_sizes, int n_in,
                              void* d_out, int out_size)
{
    (void)in_sizes; (void)n_in; (void)out_size;

    const float* context = (const float*)d_in[1];
    const float* Wkv     = (const float*)d_in[4];
    const float* bkv     = (const float*)d_in[5];
    const float* Wo      = (const float*)d_in[6];
    const float* bo      = (const float*)d_in[7];
    float* out           = (float*)d_out;

    static bool attr_set = false;
    if (!attr_set) {
        cudaFuncSetAttribute(fused_all, cudaFuncAttributeMaxDynamicSharedMemorySize, SMEM_TOTAL);
        attr_set = true;
    }

    fused_all<<<GRID, NTHR, SMEM_TOTAL>>>(context, Wkv, bkv, Wo, bo, out);
}